// round 6
// baseline (speedup 1.0000x reference)
#include <cuda_runtime.h>

// Residual_74629351735837 — bundle-adjustment reprojection residual.
// inputs: poses f32[C,7], points f32[P,3], observes f32[P,2], K f32[3,3],
//         cidx i32[P], pidx i32[P]  -> out f32[P,2]
//
// Numerics: near-singular Z points dominate the norm; Z's rounding chain must
// match XLA/LLVM fp-contract=fast fusion:
//   cross  = fma(a, b, -rn(c*d))          (fsub(fmul,fmul): operand-0 fused)
//   uv     = fma(qw, p, cross)            (fadd(x, fmul): operand-1 fused)
//   cross2 = fma(a, u, -rn(c*u'))
//   pc     = rn(rn(p + 2*cross2) + t)     (mul by 2 exact)

__global__ __launch_bounds__(256) void residual_kernel(
    const float* __restrict__ poses,
    const float* __restrict__ points,
    const float2* __restrict__ observes,
    const float* __restrict__ Kmat,
    const int* __restrict__ cidx,
    const int* __restrict__ pidx,
    float2* __restrict__ out,
    int P)
{
    int i = blockIdx.x * blockDim.x + threadIdx.x;
    if (i >= P) return;

    float k00 = __ldg(Kmat + 0), k01 = __ldg(Kmat + 1), k02 = __ldg(Kmat + 2);
    float k10 = __ldg(Kmat + 3), k11 = __ldg(Kmat + 4), k12 = __ldg(Kmat + 5);
    float k20 = __ldg(Kmat + 6), k21 = __ldg(Kmat + 7), k22 = __ldg(Kmat + 8);

    int c = __ldg(cidx + i);
    int p = __ldg(pidx + i);

    const float* pose = poses + (long long)c * 7;
    float tx = __ldg(pose + 0), ty = __ldg(pose + 1), tz = __ldg(pose + 2);
    float qx = __ldg(pose + 3), qy = __ldg(pose + 4), qz = __ldg(pose + 5);
    float qw = __ldg(pose + 6);

    const float* pt = points + (long long)p * 3;
    float px = __ldg(pt + 0), py = __ldg(pt + 1), pz = __ldg(pt + 2);

    // cross(qv, p): fma(a, b, -rn(c*d))
    float crx = __fmaf_rn(qy, pz, -__fmul_rn(qz, py));
    float cry = __fmaf_rn(qz, px, -__fmul_rn(qx, pz));
    float crz = __fmaf_rn(qx, py, -__fmul_rn(qy, px));

    // uv = cross + qw*p: fma(qw, p, cross)
    float ux = __fmaf_rn(qw, px, crx);
    float uy = __fmaf_rn(qw, py, cry);
    float uz = __fmaf_rn(qw, pz, crz);

    // cross(qv, uv): same fusion pattern
    float cx2 = __fmaf_rn(qy, uz, -__fmul_rn(qz, uy));
    float cy2 = __fmaf_rn(qz, ux, -__fmul_rn(qx, uz));
    float cz2 = __fmaf_rn(qx, uy, -__fmul_rn(qy, ux));

    // pc = (p + 2*cross2) + t   (2*c exact, so fma(2,c,p) == rn(p + 2c))
    float X = __fadd_rn(__fmaf_rn(2.0f, cx2, px), tx);
    float Y = __fadd_rn(__fmaf_rn(2.0f, cy2, py), ty);
    float Z = __fadd_rn(__fmaf_rn(2.0f, cz2, pz), tz);

    // proj = pc @ K^T, fma accumulation over k=0,1,2 from zero:
    // acc = rn(X*k0); acc = fma(Y,k1,acc); acc = fma(Z,k2,acc)
    float pr0 = __fmaf_rn(Z, k02, __fmaf_rn(Y, k01, __fmul_rn(X, k00)));
    float pr1 = __fmaf_rn(Z, k12, __fmaf_rn(Y, k11, __fmul_rn(X, k10)));
    float pr2 = __fmaf_rn(Z, k22, __fmaf_rn(Y, k21, __fmul_rn(X, k20)));

    float2 ob = __ldg(observes + i);
    float rx = __fsub_rn(__fdiv_rn(pr0, pr2), ob.x);
    float ry = __fsub_rn(__fdiv_rn(pr1, pr2), ob.y);
    out[i] = make_float2(rx, ry);
}

extern "C" void kernel_launch(void* const* d_in, const int* in_sizes, int n_in,
                              void* d_out, int out_size)
{
    const float*  poses    = (const float*)d_in[0];
    const float*  points   = (const float*)d_in[1];
    const float2* observes = (const float2*)d_in[2];
    const float*  Kmat     = (const float*)d_in[3];
    const int*    cidx     = (const int*)d_in[4];
    const int*    pidx     = (const int*)d_in[5];
    float2*       out      = (float2*)d_out;

    int P = in_sizes[4];

    const int threads = 256;
    int blocks = (P + threads - 1) / threads;
    residual_kernel<<<blocks, threads>>>(poses, points, observes, Kmat,
                                         cidx, pidx, out, P);
}

// round 7
// speedup vs baseline: 1.0326x; 1.0326x over previous
#include <cuda_runtime.h>

// Residual_74629351735837 — bundle-adjustment reprojection residual.
// 4 points per thread, vectorized streaming loads, scalar L2-resident pose gather.
// NUMERICS FROZEN: the fma/mul chain below matched the reference at rel_err
// 9.9e-4 — do not alter any rounding operation.

__device__ __forceinline__ void compute_one(
    float tx, float ty, float tz, float qx, float qy, float qz, float qw,
    float px, float py, float pz,
    float k00, float k01, float k02, float k10, float k11, float k12,
    float k20, float k21, float k22,
    float obx, float oby, float& rx, float& ry)
{
    // cross(qv, p): fma(a, b, -rn(c*d))
    float crx = __fmaf_rn(qy, pz, -__fmul_rn(qz, py));
    float cry = __fmaf_rn(qz, px, -__fmul_rn(qx, pz));
    float crz = __fmaf_rn(qx, py, -__fmul_rn(qy, px));
    // uv = cross + qw*p
    float ux = __fmaf_rn(qw, px, crx);
    float uy = __fmaf_rn(qw, py, cry);
    float uz = __fmaf_rn(qw, pz, crz);
    // cross(qv, uv)
    float cx2 = __fmaf_rn(qy, uz, -__fmul_rn(qz, uy));
    float cy2 = __fmaf_rn(qz, ux, -__fmul_rn(qx, uz));
    float cz2 = __fmaf_rn(qx, uy, -__fmul_rn(qy, ux));
    // pc = (p + 2*cross2) + t
    float X = __fadd_rn(__fmaf_rn(2.0f, cx2, px), tx);
    float Y = __fadd_rn(__fmaf_rn(2.0f, cy2, py), ty);
    float Z = __fadd_rn(__fmaf_rn(2.0f, cz2, pz), tz);
    // proj = pc @ K^T
    float pr0 = __fmaf_rn(Z, k02, __fmaf_rn(Y, k01, __fmul_rn(X, k00)));
    float pr1 = __fmaf_rn(Z, k12, __fmaf_rn(Y, k11, __fmul_rn(X, k10)));
    float pr2 = __fmaf_rn(Z, k22, __fmaf_rn(Y, k21, __fmul_rn(X, k20)));
    rx = __fsub_rn(__fdiv_rn(pr0, pr2), obx);
    ry = __fsub_rn(__fdiv_rn(pr1, pr2), oby);
}

__global__ __launch_bounds__(128) void residual_kernel4(
    const float* __restrict__ poses,
    const float* __restrict__ points,
    const float* __restrict__ observes,
    const float* __restrict__ Kmat,
    const int* __restrict__ cidx,
    const int* __restrict__ pidx,
    float* __restrict__ out,
    int P)
{
    int t = blockIdx.x * blockDim.x + threadIdx.x;
    int base = t * 4;
    if (base >= P) return;

    float k00 = __ldg(Kmat + 0), k01 = __ldg(Kmat + 1), k02 = __ldg(Kmat + 2);
    float k10 = __ldg(Kmat + 3), k11 = __ldg(Kmat + 4), k12 = __ldg(Kmat + 5);
    float k20 = __ldg(Kmat + 6), k21 = __ldg(Kmat + 7), k22 = __ldg(Kmat + 8);

    if (base + 3 < P) {
        // ---- fast path: fully vectorized streaming ----
        int4 ci = __ldg((const int4*)cidx + t);
        int4 pi = __ldg((const int4*)pidx + t);

        float pxv[4], pyv[4], pzv[4];
        bool ident = (pi.x == base) & (pi.y == base + 1) &
                     (pi.z == base + 2) & (pi.w == base + 3);
        if (ident) {
            // 4 consecutive points = 12 floats = 3 float4 loads (48B aligned: 48*t)
            const float4* pb = (const float4*)(points) + 3 * t;
            float4 a = __ldg(pb + 0);
            float4 b = __ldg(pb + 1);
            float4 d = __ldg(pb + 2);
            pxv[0] = a.x; pyv[0] = a.y; pzv[0] = a.z;
            pxv[1] = a.w; pyv[1] = b.x; pzv[1] = b.y;
            pxv[2] = b.z; pyv[2] = b.w; pzv[2] = d.x;
            pxv[3] = d.y; pyv[3] = d.z; pzv[3] = d.w;
        } else {
            int piv[4] = {pi.x, pi.y, pi.z, pi.w};
#pragma unroll
            for (int j = 0; j < 4; j++) {
                const float* pt = points + (long long)piv[j] * 3;
                pxv[j] = __ldg(pt + 0); pyv[j] = __ldg(pt + 1); pzv[j] = __ldg(pt + 2);
            }
        }

        // pose gather: 28 independent scalar L2-resident loads
        int civ[4] = {ci.x, ci.y, ci.z, ci.w};
        float txv[4], tyv[4], tzv[4], qxv[4], qyv[4], qzv[4], qwv[4];
#pragma unroll
        for (int j = 0; j < 4; j++) {
            const float* pose = poses + (long long)civ[j] * 7;
            txv[j] = __ldg(pose + 0); tyv[j] = __ldg(pose + 1); tzv[j] = __ldg(pose + 2);
            qxv[j] = __ldg(pose + 3); qyv[j] = __ldg(pose + 4); qzv[j] = __ldg(pose + 5);
            qwv[j] = __ldg(pose + 6);
        }

        // observes: 4 points = 8 floats = 2 float4
        const float4* obp = (const float4*)(observes) + 2 * t;
        float4 o0 = __ldg(obp + 0);
        float4 o1 = __ldg(obp + 1);
        float obx[4] = {o0.x, o0.z, o1.x, o1.z};
        float oby[4] = {o0.y, o0.w, o1.y, o1.w};

        float rx[4], ry[4];
#pragma unroll
        for (int j = 0; j < 4; j++) {
            compute_one(txv[j], tyv[j], tzv[j], qxv[j], qyv[j], qzv[j], qwv[j],
                        pxv[j], pyv[j], pzv[j],
                        k00, k01, k02, k10, k11, k12, k20, k21, k22,
                        obx[j], oby[j], rx[j], ry[j]);
        }

        float4* ob4 = (float4*)(out) + 2 * t;
        ob4[0] = make_float4(rx[0], ry[0], rx[1], ry[1]);
        ob4[1] = make_float4(rx[2], ry[2], rx[3], ry[3]);
    } else {
        // ---- tail: scalar per point ----
        for (int i = base; i < P; i++) {
            int c = __ldg(cidx + i);
            int p = __ldg(pidx + i);
            const float* pose = poses + (long long)c * 7;
            const float* pt = points + (long long)p * 3;
            float rx, ry;
            compute_one(__ldg(pose + 0), __ldg(pose + 1), __ldg(pose + 2),
                        __ldg(pose + 3), __ldg(pose + 4), __ldg(pose + 5), __ldg(pose + 6),
                        __ldg(pt + 0), __ldg(pt + 1), __ldg(pt + 2),
                        k00, k01, k02, k10, k11, k12, k20, k21, k22,
                        __ldg(observes + 2 * i), __ldg(observes + 2 * i + 1), rx, ry);
            out[2 * i] = rx;
            out[2 * i + 1] = ry;
        }
    }
}

extern "C" void kernel_launch(void* const* d_in, const int* in_sizes, int n_in,
                              void* d_out, int out_size)
{
    const float* poses    = (const float*)d_in[0];
    const float* points   = (const float*)d_in[1];
    const float* observes = (const float*)d_in[2];
    const float* Kmat     = (const float*)d_in[3];
    const int*   cidx     = (const int*)d_in[4];
    const int*   pidx     = (const int*)d_in[5];
    float*       out      = (float*)d_out;

    int P = in_sizes[4];

    const int threads = 128;
    int elemsPerBlock = threads * 4;
    int blocks = (P + elemsPerBlock - 1) / elemsPerBlock;
    residual_kernel4<<<blocks, threads>>>(poses, points, observes, Kmat,
                                          cidx, pidx, out, P);
}

// round 8
// speedup vs baseline: 1.2699x; 1.2298x over previous
#include <cuda_runtime.h>

// Residual_74629351735837 — bundle-adjustment reprojection residual.
// R8: pose table staged in shared memory (56KB, kills the L1tex gather
// bottleneck), persistent grid-stride over groups of 4 points, vectorized
// streaming loads/stores.
// NUMERICS FROZEN: compute_one matched the reference at rel_err 9.9e-4 —
// do not alter any rounding operation.

__device__ __forceinline__ void compute_one(
    float tx, float ty, float tz, float qx, float qy, float qz, float qw,
    float px, float py, float pz,
    float k00, float k01, float k02, float k10, float k11, float k12,
    float k20, float k21, float k22,
    float obx, float oby, float& rx, float& ry)
{
    float crx = __fmaf_rn(qy, pz, -__fmul_rn(qz, py));
    float cry = __fmaf_rn(qz, px, -__fmul_rn(qx, pz));
    float crz = __fmaf_rn(qx, py, -__fmul_rn(qy, px));
    float ux = __fmaf_rn(qw, px, crx);
    float uy = __fmaf_rn(qw, py, cry);
    float uz = __fmaf_rn(qw, pz, crz);
    float cx2 = __fmaf_rn(qy, uz, -__fmul_rn(qz, uy));
    float cy2 = __fmaf_rn(qz, ux, -__fmul_rn(qx, uz));
    float cz2 = __fmaf_rn(qx, uy, -__fmul_rn(qy, ux));
    float X = __fadd_rn(__fmaf_rn(2.0f, cx2, px), tx);
    float Y = __fadd_rn(__fmaf_rn(2.0f, cy2, py), ty);
    float Z = __fadd_rn(__fmaf_rn(2.0f, cz2, pz), tz);
    float pr0 = __fmaf_rn(Z, k02, __fmaf_rn(Y, k01, __fmul_rn(X, k00)));
    float pr1 = __fmaf_rn(Z, k12, __fmaf_rn(Y, k11, __fmul_rn(X, k10)));
    float pr2 = __fmaf_rn(Z, k22, __fmaf_rn(Y, k21, __fmul_rn(X, k20)));
    rx = __fsub_rn(__fdiv_rn(pr0, pr2), obx);
    ry = __fsub_rn(__fdiv_rn(pr1, pr2), oby);
}

__global__ __launch_bounds__(256) void residual_smem_kernel(
    const float* __restrict__ poses,
    const float* __restrict__ points,
    const float* __restrict__ observes,
    const float* __restrict__ Kmat,
    const int* __restrict__ cidx,
    const int* __restrict__ pidx,
    float* __restrict__ out,
    int P, int nPoseFloats)
{
    extern __shared__ float sm_poses[];

    // Cooperative stage of the full pose table into smem (float4 main + tail).
    int tid = threadIdx.x;
    int nv4 = nPoseFloats >> 2;
    const float4* pose4 = (const float4*)poses;
    float4* sm4 = (float4*)sm_poses;
    for (int i = tid; i < nv4; i += blockDim.x) sm4[i] = __ldg(pose4 + i);
    for (int i = (nv4 << 2) + tid; i < nPoseFloats; i += blockDim.x)
        sm_poses[i] = __ldg(poses + i);
    __syncthreads();

    float k00 = __ldg(Kmat + 0), k01 = __ldg(Kmat + 1), k02 = __ldg(Kmat + 2);
    float k10 = __ldg(Kmat + 3), k11 = __ldg(Kmat + 4), k12 = __ldg(Kmat + 5);
    float k20 = __ldg(Kmat + 6), k21 = __ldg(Kmat + 7), k22 = __ldg(Kmat + 8);

    int G = (P + 3) >> 2;  // groups of 4 points
    int stride = gridDim.x * blockDim.x;

    for (int t = blockIdx.x * blockDim.x + tid; t < G; t += stride) {
        int base = t * 4;
        if (base + 3 < P) {
            // ---- fast path ----
            int4 ci = __ldg((const int4*)cidx + t);
            int4 pi = __ldg((const int4*)pidx + t);

            float pxv[4], pyv[4], pzv[4];
            bool ident = (pi.x == base) & (pi.y == base + 1) &
                         (pi.z == base + 2) & (pi.w == base + 3);
            if (ident) {
                const float4* pb = (const float4*)(points) + 3 * t;
                float4 a = __ldg(pb + 0);
                float4 b = __ldg(pb + 1);
                float4 d = __ldg(pb + 2);
                pxv[0] = a.x; pyv[0] = a.y; pzv[0] = a.z;
                pxv[1] = a.w; pyv[1] = b.x; pzv[1] = b.y;
                pxv[2] = b.z; pyv[2] = b.w; pzv[2] = d.x;
                pxv[3] = d.y; pyv[3] = d.z; pzv[3] = d.w;
            } else {
                int piv[4] = {pi.x, pi.y, pi.z, pi.w};
#pragma unroll
                for (int j = 0; j < 4; j++) {
                    const float* pt = points + (long long)piv[j] * 3;
                    pxv[j] = __ldg(pt + 0); pyv[j] = __ldg(pt + 1); pzv[j] = __ldg(pt + 2);
                }
            }

            // pose gather from SMEM (stride-7 -> banks well distributed)
            int civ[4] = {ci.x, ci.y, ci.z, ci.w};
            float txv[4], tyv[4], tzv[4], qxv[4], qyv[4], qzv[4], qwv[4];
#pragma unroll
            for (int j = 0; j < 4; j++) {
                const float* sp = sm_poses + civ[j] * 7;
                txv[j] = sp[0]; tyv[j] = sp[1]; tzv[j] = sp[2];
                qxv[j] = sp[3]; qyv[j] = sp[4]; qzv[j] = sp[5];
                qwv[j] = sp[6];
            }

            const float4* obp = (const float4*)(observes) + 2 * t;
            float4 o0 = __ldg(obp + 0);
            float4 o1 = __ldg(obp + 1);
            float obx[4] = {o0.x, o0.z, o1.x, o1.z};
            float oby[4] = {o0.y, o0.w, o1.y, o1.w};

            float rx[4], ry[4];
#pragma unroll
            for (int j = 0; j < 4; j++) {
                compute_one(txv[j], tyv[j], tzv[j], qxv[j], qyv[j], qzv[j], qwv[j],
                            pxv[j], pyv[j], pzv[j],
                            k00, k01, k02, k10, k11, k12, k20, k21, k22,
                            obx[j], oby[j], rx[j], ry[j]);
            }

            float4* ob4 = (float4*)(out) + 2 * t;
            ob4[0] = make_float4(rx[0], ry[0], rx[1], ry[1]);
            ob4[1] = make_float4(rx[2], ry[2], rx[3], ry[3]);
        } else {
            // ---- tail ----
            for (int i = base; i < P; i++) {
                int c = __ldg(cidx + i);
                int p = __ldg(pidx + i);
                const float* sp = sm_poses + c * 7;
                const float* pt = points + (long long)p * 3;
                float rx, ry;
                compute_one(sp[0], sp[1], sp[2], sp[3], sp[4], sp[5], sp[6],
                            __ldg(pt + 0), __ldg(pt + 1), __ldg(pt + 2),
                            k00, k01, k02, k10, k11, k12, k20, k21, k22,
                            __ldg(observes + 2 * i), __ldg(observes + 2 * i + 1),
                            rx, ry);
                out[2 * i] = rx;
                out[2 * i + 1] = ry;
            }
        }
    }
}

// Fallback (pose table too big for smem): R7 kernel, gather from gmem.
__global__ __launch_bounds__(128) void residual_gmem_kernel(
    const float* __restrict__ poses,
    const float* __restrict__ points,
    const float* __restrict__ observes,
    const float* __restrict__ Kmat,
    const int* __restrict__ cidx,
    const int* __restrict__ pidx,
    float* __restrict__ out,
    int P)
{
    int t = blockIdx.x * blockDim.x + threadIdx.x;
    int base = t * 4;
    if (base >= P) return;

    float k00 = __ldg(Kmat + 0), k01 = __ldg(Kmat + 1), k02 = __ldg(Kmat + 2);
    float k10 = __ldg(Kmat + 3), k11 = __ldg(Kmat + 4), k12 = __ldg(Kmat + 5);
    float k20 = __ldg(Kmat + 6), k21 = __ldg(Kmat + 7), k22 = __ldg(Kmat + 8);

    for (int i = base; i < P && i < base + 4; i++) {
        int c = __ldg(cidx + i);
        int p = __ldg(pidx + i);
        const float* pose = poses + (long long)c * 7;
        const float* pt = points + (long long)p * 3;
        float rx, ry;
        compute_one(__ldg(pose + 0), __ldg(pose + 1), __ldg(pose + 2),
                    __ldg(pose + 3), __ldg(pose + 4), __ldg(pose + 5), __ldg(pose + 6),
                    __ldg(pt + 0), __ldg(pt + 1), __ldg(pt + 2),
                    k00, k01, k02, k10, k11, k12, k20, k21, k22,
                    __ldg(observes + 2 * i), __ldg(observes + 2 * i + 1), rx, ry);
        out[2 * i] = rx;
        out[2 * i + 1] = ry;
    }
}

extern "C" void kernel_launch(void* const* d_in, const int* in_sizes, int n_in,
                              void* d_out, int out_size)
{
    const float* poses    = (const float*)d_in[0];
    const float* points   = (const float*)d_in[1];
    const float* observes = (const float*)d_in[2];
    const float* Kmat     = (const float*)d_in[3];
    const int*   cidx     = (const int*)d_in[4];
    const int*   pidx     = (const int*)d_in[5];
    float*       out      = (float*)d_out;

    int P = in_sizes[4];
    int nPoseFloats = in_sizes[0];          // C * 7
    size_t smemBytes = (size_t)nPoseFloats * sizeof(float);

    if (smemBytes <= 200 * 1024) {
        static bool attrSet = false;
        if (!attrSet) {
            cudaFuncSetAttribute(residual_smem_kernel,
                                 cudaFuncAttributeMaxDynamicSharedMemorySize,
                                 227 * 1024);
            attrSet = true;
        }
        const int threads = 256;
        // 4 blocks/SM at 56KB smem; 148 SMs -> 592 resident blocks.
        int G = (P + 3) >> 2;
        int maxBlocks = 592;
        int needBlocks = (G + threads - 1) / threads;
        int blocks = needBlocks < maxBlocks ? needBlocks : maxBlocks;
        residual_smem_kernel<<<blocks, threads, smemBytes>>>(
            poses, points, observes, Kmat, cidx, pidx, out, P, nPoseFloats);
    } else {
        const int threads = 128;
        int elemsPerBlock = threads * 4;
        int blocks = (P + elemsPerBlock - 1) / elemsPerBlock;
        residual_gmem_kernel<<<blocks, threads>>>(
            poses, points, observes, Kmat, cidx, pidx, out, P);
    }
}